// round 1
// baseline (speedup 1.0000x reference)
#include <cuda_runtime.h>

// Problem constants
#define BATCH   4
#define TSEQ    2048
#define CDIM    1024
#define NHEADS  16
#define HDIM    64
#define MROWS   (BATCH * TSEQ)     // 8192
#define NQKV    (3 * CDIM)         // 3072

// Scratch (allocation-free rule: __device__ globals)
__device__ float g_Q[(size_t)BATCH * NHEADS * TSEQ * HDIM];   // (B,H,T,Dh)
__device__ float g_K[(size_t)BATCH * NHEADS * TSEQ * HDIM];
__device__ float g_V[(size_t)BATCH * NHEADS * TSEQ * HDIM];
__device__ float g_Y[(size_t)MROWS * CDIM];                    // (B,T,C) attention output

// ---------------------------------------------------------------------------
// Kernel 1: qkv = x @ w_qkv + b_qkv, scattered into head-major Q/K/V.
// 64x64 output tile, BK=16, 256 threads, 4x4 microtile per thread.
// ---------------------------------------------------------------------------
__global__ __launch_bounds__(256) void qkv_gemm_kernel(
    const float* __restrict__ X,      // (8192, 1024)
    const float* __restrict__ W,      // (1024, 3072)
    const float* __restrict__ bias)   // (3072,)
{
    __shared__ float As[16][64];      // [k][m]
    __shared__ float Bs[16][64];      // [k][n]

    const int tid  = threadIdx.x;
    const int tx   = tid & 15;
    const int ty   = tid >> 4;
    const int row0 = blockIdx.y * 64;
    const int col0 = blockIdx.x * 64;

    const int ar  = tid >> 2;         // 0..63   A row within tile
    const int ak4 = (tid & 3) * 4;    // 0,4,8,12 A k-offset
    const int bk  = tid >> 4;         // 0..15   B k-row
    const int bc4 = (tid & 15) * 4;   // 0..60   B col offset

    float acc[4][4] = {};

    for (int k0 = 0; k0 < CDIM; k0 += 16) {
        float4 a = *(const float4*)(X + (size_t)(row0 + ar) * CDIM + k0 + ak4);
        As[ak4 + 0][ar] = a.x;
        As[ak4 + 1][ar] = a.y;
        As[ak4 + 2][ar] = a.z;
        As[ak4 + 3][ar] = a.w;
        *(float4*)(&Bs[bk][bc4]) =
            *(const float4*)(W + (size_t)(k0 + bk) * NQKV + col0 + bc4);
        __syncthreads();

#pragma unroll
        for (int kk = 0; kk < 16; kk++) {
            float4 av = *(const float4*)(&As[kk][ty * 4]);
            float4 bv = *(const float4*)(&Bs[kk][tx * 4]);
            float aa[4] = {av.x, av.y, av.z, av.w};
            float bb[4] = {bv.x, bv.y, bv.z, bv.w};
#pragma unroll
            for (int i = 0; i < 4; i++)
#pragma unroll
                for (int j = 0; j < 4; j++)
                    acc[i][j] += aa[i] * bb[j];
        }
        __syncthreads();
    }

    // Epilogue: whole block maps to one (s, h) since col tile width == HDIM.
    const int s  = col0 / CDIM;                 // 0=Q 1=K 2=V
    const int h  = (col0 % CDIM) / HDIM;
    const int b  = row0 / TSEQ;
    const int t0 = row0 % TSEQ;
    float* dst = (s == 0) ? g_Q : (s == 1) ? g_K : g_V;
    const size_t base = (size_t)(b * NHEADS + h) * TSEQ * HDIM;

    float bb[4];
#pragma unroll
    for (int j = 0; j < 4; j++) bb[j] = bias[col0 + tx * 4 + j];

#pragma unroll
    for (int i = 0; i < 4; i++) {
        const int t = t0 + ty * 4 + i;
        float4 v;
        v.x = acc[i][0] + bb[0];
        v.y = acc[i][1] + bb[1];
        v.z = acc[i][2] + bb[2];
        v.w = acc[i][3] + bb[3];
        *(float4*)(dst + base + (size_t)t * HDIM + tx * 4) = v;
    }
}

// ---------------------------------------------------------------------------
// Kernel 2: causal flash attention, fp32 online softmax.
// Block = 64 query rows, inner loop over 32-key tiles. 256 threads.
// S microtile 4x2 per thread (rows ty*4.., cols tx*2..); O microtile 4x4.
// ---------------------------------------------------------------------------
__global__ __launch_bounds__(256) void attn_kernel()
{
    __shared__ float Qs[64][65];
    __shared__ float Ks[32][65];
    __shared__ float Vs[32][65];
    __shared__ float Ps[64][33];

    const int tid = threadIdx.x;
    const int tx  = tid & 15;
    const int ty  = tid >> 4;
    const int bh  = blockIdx.y;           // b*16 + h
    const int q0  = blockIdx.x * 64;

    const float* Qg = g_Q + (size_t)bh * TSEQ * HDIM;
    const float* Kg = g_K + (size_t)bh * TSEQ * HDIM;
    const float* Vg = g_V + (size_t)bh * TSEQ * HDIM;

    const float scale = 0.125f;           // 1/sqrt(64)

    // Load + pre-scale Q tile (64x64)
#pragma unroll
    for (int c = 0; c < 4; c++) {
        const int f   = c * 1024 + tid * 4;
        const int r   = f >> 6;
        const int col = f & 63;
        float4 v = *(const float4*)(Qg + (size_t)(q0 + r) * HDIM + col);
        Qs[r][col + 0] = v.x * scale;
        Qs[r][col + 1] = v.y * scale;
        Qs[r][col + 2] = v.z * scale;
        Qs[r][col + 3] = v.w * scale;
    }

    float o[4][4] = {};
    float mrow[4] = {-1e30f, -1e30f, -1e30f, -1e30f};
    float lrow[4] = {};

    const int nkt = 2 * blockIdx.x + 2;   // key tiles covering k <= q0+63

    for (int kt = 0; kt < nkt; kt++) {
        const int k0 = kt * 32;
        // Load K,V tiles (32x64 each)
#pragma unroll
        for (int c = 0; c < 2; c++) {
            const int f   = c * 1024 + tid * 4;
            const int r   = f >> 6;
            const int col = f & 63;
            float4 kv = *(const float4*)(Kg + (size_t)(k0 + r) * HDIM + col);
            Ks[r][col + 0] = kv.x;
            Ks[r][col + 1] = kv.y;
            Ks[r][col + 2] = kv.z;
            Ks[r][col + 3] = kv.w;
            float4 vv = *(const float4*)(Vg + (size_t)(k0 + r) * HDIM + col);
            Vs[r][col + 0] = vv.x;
            Vs[r][col + 1] = vv.y;
            Vs[r][col + 2] = vv.z;
            Vs[r][col + 3] = vv.w;
        }
        __syncthreads();

        // S = Q K^T (scaled already); 4x2 micro
        float sacc[4][2] = {};
#pragma unroll
        for (int d = 0; d < 64; d++) {
            float qf[4], kf[2];
#pragma unroll
            for (int i = 0; i < 4; i++) qf[i] = Qs[ty * 4 + i][d];
            kf[0] = Ks[tx * 2 + 0][d];
            kf[1] = Ks[tx * 2 + 1][d];
#pragma unroll
            for (int i = 0; i < 4; i++) {
                sacc[i][0] += qf[i] * kf[0];
                sacc[i][1] += qf[i] * kf[1];
            }
        }

        // Causal mask (cheap; applied every tile)
#pragma unroll
        for (int i = 0; i < 4; i++)
#pragma unroll
            for (int j = 0; j < 2; j++) {
                const int q = q0 + ty * 4 + i;
                const int k = k0 + tx * 2 + j;
                if (k > q) sacc[i][j] = -1e30f;
            }

        // Online softmax update; row group = 16 lanes within half-warp
#pragma unroll
        for (int i = 0; i < 4; i++) {
            float mx = fmaxf(sacc[i][0], sacc[i][1]);
#pragma unroll
            for (int off = 8; off >= 1; off >>= 1)
                mx = fmaxf(mx, __shfl_xor_sync(0xffffffffu, mx, off));
            const float mnew = fmaxf(mrow[i], mx);
            const float p0 = __expf(sacc[i][0] - mnew);
            const float p1 = __expf(sacc[i][1] - mnew);
            float rs = p0 + p1;
#pragma unroll
            for (int off = 8; off >= 1; off >>= 1)
                rs += __shfl_xor_sync(0xffffffffu, rs, off);
            const float corr = __expf(mrow[i] - mnew);
            lrow[i] = lrow[i] * corr + rs;
            mrow[i] = mnew;
#pragma unroll
            for (int j = 0; j < 4; j++) o[i][j] *= corr;
            Ps[ty * 4 + i][tx * 2 + 0] = p0;
            Ps[ty * 4 + i][tx * 2 + 1] = p1;
        }
        __syncthreads();

        // O += P @ V ; 4x4 micro over (row, d)
#pragma unroll
        for (int k = 0; k < 32; k++) {
            float pf[4], vf[4];
#pragma unroll
            for (int i = 0; i < 4; i++) pf[i] = Ps[ty * 4 + i][k];
#pragma unroll
            for (int j = 0; j < 4; j++) vf[j] = Vs[k][tx * 4 + j];
#pragma unroll
            for (int i = 0; i < 4; i++)
#pragma unroll
                for (int j = 0; j < 4; j++)
                    o[i][j] += pf[i] * vf[j];
        }
        __syncthreads();   // protect Ks/Vs/Ps for next iteration
    }

    // Normalize and write to (B,T,C) layout for the proj GEMM
    const int b = bh >> 4;
    const int h = bh & 15;
#pragma unroll
    for (int i = 0; i < 4; i++) {
        const float inv = 1.0f / lrow[i];
        const int t = q0 + ty * 4 + i;
        float4 v;
        v.x = o[i][0] * inv;
        v.y = o[i][1] * inv;
        v.z = o[i][2] * inv;
        v.w = o[i][3] * inv;
        *(float4*)(g_Y + (size_t)(b * TSEQ + t) * CDIM + h * HDIM + tx * 4) = v;
    }
}

// ---------------------------------------------------------------------------
// Kernel 3: out = Y @ w_proj + b_proj
// ---------------------------------------------------------------------------
__global__ __launch_bounds__(256) void proj_gemm_kernel(
    const float* __restrict__ W,      // (1024, 1024)
    const float* __restrict__ bias,   // (1024,)
    float* __restrict__ out)          // (8192, 1024)
{
    __shared__ float As[16][64];
    __shared__ float Bs[16][64];

    const int tid  = threadIdx.x;
    const int tx   = tid & 15;
    const int ty   = tid >> 4;
    const int row0 = blockIdx.y * 64;
    const int col0 = blockIdx.x * 64;

    const int ar  = tid >> 2;
    const int ak4 = (tid & 3) * 4;
    const int bk  = tid >> 4;
    const int bc4 = (tid & 15) * 4;

    float acc[4][4] = {};

    for (int k0 = 0; k0 < CDIM; k0 += 16) {
        float4 a = *(const float4*)(g_Y + (size_t)(row0 + ar) * CDIM + k0 + ak4);
        As[ak4 + 0][ar] = a.x;
        As[ak4 + 1][ar] = a.y;
        As[ak4 + 2][ar] = a.z;
        As[ak4 + 3][ar] = a.w;
        *(float4*)(&Bs[bk][bc4]) =
            *(const float4*)(W + (size_t)(k0 + bk) * CDIM + col0 + bc4);
        __syncthreads();

#pragma unroll
        for (int kk = 0; kk < 16; kk++) {
            float4 av = *(const float4*)(&As[kk][ty * 4]);
            float4 bv = *(const float4*)(&Bs[kk][tx * 4]);
            float aa[4] = {av.x, av.y, av.z, av.w};
            float bb[4] = {bv.x, bv.y, bv.z, bv.w};
#pragma unroll
            for (int i = 0; i < 4; i++)
#pragma unroll
                for (int j = 0; j < 4; j++)
                    acc[i][j] += aa[i] * bb[j];
        }
        __syncthreads();
    }

    float bb[4];
#pragma unroll
    for (int j = 0; j < 4; j++) bb[j] = bias[col0 + tx * 4 + j];

#pragma unroll
    for (int i = 0; i < 4; i++) {
        float4 v;
        v.x = acc[i][0] + bb[0];
        v.y = acc[i][1] + bb[1];
        v.z = acc[i][2] + bb[2];
        v.w = acc[i][3] + bb[3];
        *(float4*)(out + (size_t)(row0 + ty * 4 + i) * CDIM + col0 + tx * 4) = v;
    }
}

// ---------------------------------------------------------------------------
extern "C" void kernel_launch(void* const* d_in, const int* in_sizes, int n_in,
                              void* d_out, int out_size)
{
    const float* x      = (const float*)d_in[0];
    const float* w_qkv  = (const float*)d_in[1];
    const float* b_qkv  = (const float*)d_in[2];
    const float* w_proj = (const float*)d_in[3];
    const float* b_proj = (const float*)d_in[4];
    float* out = (float*)d_out;

    qkv_gemm_kernel<<<dim3(NQKV / 64, MROWS / 64), 256>>>(x, w_qkv, b_qkv);
    attn_kernel<<<dim3(TSEQ / 64, BATCH * NHEADS), 256>>>();
    proj_gemm_kernel<<<dim3(CDIM / 64, MROWS / 64), 256>>>(w_proj, b_proj, out);
}

// round 3
// speedup vs baseline: 1.1862x; 1.1862x over previous
#include <cuda_runtime.h>

// Problem constants
#define BATCH   4
#define TSEQ    2048
#define CDIM    1024
#define NHEADS  16
#define HDIM    64
#define MROWS   (BATCH * TSEQ)     // 8192
#define NQKV    (3 * CDIM)         // 3072

// Scratch (allocation-free rule: __device__ globals)
__device__ float g_Q[(size_t)BATCH * NHEADS * TSEQ * HDIM];   // (B,H,T,Dh)
__device__ float g_K[(size_t)BATCH * NHEADS * TSEQ * HDIM];
__device__ float g_V[(size_t)BATCH * NHEADS * TSEQ * HDIM];
__device__ float g_Y[(size_t)MROWS * CDIM];                    // (B,T,C)

// ---------------------------------------------------------------------------
// Kernel 1: qkv = x @ w_qkv + b_qkv, scattered head-major.
// 128x128x8 tile, 256 threads, 8x8 microtile (2x2 quadrants of 4x4).
// Single smem buffer, register prefetch of next gmem tile before compute.
// ---------------------------------------------------------------------------
__global__ __launch_bounds__(256) void qkv_gemm128(
    const float* __restrict__ A,      // x (8192, 1024)
    const float* __restrict__ B,      // w_qkv (1024, 3072)
    const float* __restrict__ bias)   // (3072,)
{
    __shared__ __align__(16) float As[8][132];   // [k][m] transposed, padded
    __shared__ __align__(16) float Bs[8][128];   // [k][n]

    const int tid  = threadIdx.x;
    const int row0 = blockIdx.y * 128;
    const int col0 = blockIdx.x * 128;

    const int w    = tid >> 5;
    const int wr   = w >> 1;              // 0..3
    const int wc   = w & 1;               // 0..1
    const int lane = tid & 31;
    const int lr   = lane >> 3;           // 0..3
    const int lc   = lane & 7;            // 0..7
    const int mrow = wr * 32 + lr * 4;    // rows {mrow..+3, mrow+16..+19}
    const int ncol = wc * 64 + lc * 4;    // cols {ncol..+3, ncol+32..+35}

    const int arow = tid >> 1;            // 0..127
    const int acol = (tid & 1) * 4;       // 0 or 4
    const int brow = tid >> 5;            // 0..7
    const int bcol = (tid & 31) * 4;      // 0..124

    const float* Ag = A + (size_t)(row0 + arow) * CDIM + acol;
    const float* Bg = B + (size_t)brow * NQKV + col0 + bcol;

    float4 a4 = *(const float4*)(Ag);
    float4 b4 = *(const float4*)(Bg);

    float acc[2][2][4][4] = {};

    for (int k0 = 0; k0 < CDIM; k0 += 8) {
        __syncthreads();
        As[acol + 0][arow] = a4.x;
        As[acol + 1][arow] = a4.y;
        As[acol + 2][arow] = a4.z;
        As[acol + 3][arow] = a4.w;
        *(float4*)(&Bs[brow][bcol]) = b4;
        __syncthreads();

        if (k0 + 8 < CDIM) {             // prefetch next tile into regs
            a4 = *(const float4*)(Ag + k0 + 8);
            b4 = *(const float4*)(Bg + (size_t)(k0 + 8) * NQKV);
        }

#pragma unroll
        for (int kk = 0; kk < 8; kk++) {
            float4 a0 = *(const float4*)(&As[kk][mrow]);
            float4 a1 = *(const float4*)(&As[kk][mrow + 16]);
            float4 b0 = *(const float4*)(&Bs[kk][ncol]);
            float4 b1 = *(const float4*)(&Bs[kk][ncol + 32]);
            float ar[2][4] = {{a0.x, a0.y, a0.z, a0.w}, {a1.x, a1.y, a1.z, a1.w}};
            float br[2][4] = {{b0.x, b0.y, b0.z, b0.w}, {b1.x, b1.y, b1.z, b1.w}};
#pragma unroll
            for (int im = 0; im < 2; im++)
#pragma unroll
                for (int i = 0; i < 4; i++)
#pragma unroll
                    for (int jm = 0; jm < 2; jm++)
#pragma unroll
                        for (int j = 0; j < 4; j++)
                            acc[im][jm][i][j] += ar[im][i] * br[jm][j];
        }
    }

    float bb[2][4];
#pragma unroll
    for (int jm = 0; jm < 2; jm++)
#pragma unroll
        for (int j = 0; j < 4; j++)
            bb[jm][j] = bias[col0 + ncol + jm * 32 + j];

#pragma unroll
    for (int im = 0; im < 2; im++) {
#pragma unroll
        for (int i = 0; i < 4; i++) {
            const int row = row0 + mrow + im * 16 + i;
#pragma unroll
            for (int jm = 0; jm < 2; jm++) {
                const int col = col0 + ncol + jm * 32;
                float4 v;
                v.x = acc[im][jm][i][0] + bb[jm][0];
                v.y = acc[im][jm][i][1] + bb[jm][1];
                v.z = acc[im][jm][i][2] + bb[jm][2];
                v.w = acc[im][jm][i][3] + bb[jm][3];
                const int s = col >> 10;              // 0=Q 1=K 2=V
                const int h = (col & 1023) >> 6;
                const int d = col & 63;
                const int b = row >> 11;
                const int t = row & 2047;
                float* dst = (s == 0) ? g_Q : (s == 1) ? g_K : g_V;
                *(float4*)(dst + ((size_t)(b * NHEADS + h) * TSEQ + t) * HDIM + d) = v;
            }
        }
    }
}

// ---------------------------------------------------------------------------
// Kernel 3: out = Y @ w_proj + b_proj, same 128x128x8 structure.
// ---------------------------------------------------------------------------
__global__ __launch_bounds__(256) void proj_gemm128(
    const float* __restrict__ B,      // w_proj (1024, 1024)
    const float* __restrict__ bias,   // (1024,)
    float* __restrict__ C)            // out (8192, 1024)
{
    __shared__ __align__(16) float As[8][132];
    __shared__ __align__(16) float Bs[8][128];

    const int tid  = threadIdx.x;
    const int row0 = blockIdx.y * 128;
    const int col0 = blockIdx.x * 128;

    const int w    = tid >> 5;
    const int wr   = w >> 1;
    const int wc   = w & 1;
    const int lane = tid & 31;
    const int lr   = lane >> 3;
    const int lc   = lane & 7;
    const int mrow = wr * 32 + lr * 4;
    const int ncol = wc * 64 + lc * 4;

    const int arow = tid >> 1;
    const int acol = (tid & 1) * 4;
    const int brow = tid >> 5;
    const int bcol = (tid & 31) * 4;

    const float* Ag = g_Y + (size_t)(row0 + arow) * CDIM + acol;
    const float* Bg = B + (size_t)brow * CDIM + col0 + bcol;

    float4 a4 = *(const float4*)(Ag);
    float4 b4 = *(const float4*)(Bg);

    float acc[2][2][4][4] = {};

    for (int k0 = 0; k0 < CDIM; k0 += 8) {
        __syncthreads();
        As[acol + 0][arow] = a4.x;
        As[acol + 1][arow] = a4.y;
        As[acol + 2][arow] = a4.z;
        As[acol + 3][arow] = a4.w;
        *(float4*)(&Bs[brow][bcol]) = b4;
        __syncthreads();

        if (k0 + 8 < CDIM) {
            a4 = *(const float4*)(Ag + k0 + 8);
            b4 = *(const float4*)(Bg + (size_t)(k0 + 8) * CDIM);
        }

#pragma unroll
        for (int kk = 0; kk < 8; kk++) {
            float4 a0 = *(const float4*)(&As[kk][mrow]);
            float4 a1 = *(const float4*)(&As[kk][mrow + 16]);
            float4 b0 = *(const float4*)(&Bs[kk][ncol]);
            float4 b1 = *(const float4*)(&Bs[kk][ncol + 32]);
            float ar[2][4] = {{a0.x, a0.y, a0.z, a0.w}, {a1.x, a1.y, a1.z, a1.w}};
            float br[2][4] = {{b0.x, b0.y, b0.z, b0.w}, {b1.x, b1.y, b1.z, b1.w}};
#pragma unroll
            for (int im = 0; im < 2; im++)
#pragma unroll
                for (int i = 0; i < 4; i++)
#pragma unroll
                    for (int jm = 0; jm < 2; jm++)
#pragma unroll
                        for (int j = 0; j < 4; j++)
                            acc[im][jm][i][j] += ar[im][i] * br[jm][j];
        }
    }

    float bb[2][4];
#pragma unroll
    for (int jm = 0; jm < 2; jm++)
#pragma unroll
        for (int j = 0; j < 4; j++)
            bb[jm][j] = bias[col0 + ncol + jm * 32 + j];

#pragma unroll
    for (int im = 0; im < 2; im++) {
#pragma unroll
        for (int i = 0; i < 4; i++) {
            const int row = row0 + mrow + im * 16 + i;
#pragma unroll
            for (int jm = 0; jm < 2; jm++) {
                const int col = col0 + ncol + jm * 32;
                float4 v;
                v.x = acc[im][jm][i][0] + bb[jm][0];
                v.y = acc[im][jm][i][1] + bb[jm][1];
                v.z = acc[im][jm][i][2] + bb[jm][2];
                v.w = acc[im][jm][i][3] + bb[jm][3];
                *(float4*)(C + (size_t)row * CDIM + col) = v;
            }
        }
    }
}

// ---------------------------------------------------------------------------
// Kernel 2: causal flash attention, fp32 online softmax (identical to R1).
// ---------------------------------------------------------------------------
__global__ __launch_bounds__(256) void attn_kernel()
{
    __shared__ float Qs[64][65];
    __shared__ float Ks[32][65];
    __shared__ float Vs[32][65];
    __shared__ float Ps[64][33];

    const int tid = threadIdx.x;
    const int tx  = tid & 15;
    const int ty  = tid >> 4;
    const int bh  = blockIdx.y;
    const int q0  = blockIdx.x * 64;

    const float* Qg = g_Q + (size_t)bh * TSEQ * HDIM;
    const float* Kg = g_K + (size_t)bh * TSEQ * HDIM;
    const float* Vg = g_V + (size_t)bh * TSEQ * HDIM;

    const float scale = 0.125f;

#pragma unroll
    for (int c = 0; c < 4; c++) {
        const int f   = c * 1024 + tid * 4;
        const int r   = f >> 6;
        const int col = f & 63;
        float4 v = *(const float4*)(Qg + (size_t)(q0 + r) * HDIM + col);
        Qs[r][col + 0] = v.x * scale;
        Qs[r][col + 1] = v.y * scale;
        Qs[r][col + 2] = v.z * scale;
        Qs[r][col + 3] = v.w * scale;
    }

    float o[4][4] = {};
    float mrow[4] = {-1e30f, -1e30f, -1e30f, -1e30f};
    float lrow[4] = {};

    const int nkt = 2 * blockIdx.x + 2;

    for (int kt = 0; kt < nkt; kt++) {
        const int k0 = kt * 32;
#pragma unroll
        for (int c = 0; c < 2; c++) {
            const int f   = c * 1024 + tid * 4;
            const int r   = f >> 6;
            const int col = f & 63;
            float4 kv = *(const float4*)(Kg + (size_t)(k0 + r) * HDIM + col);
            Ks[r][col + 0] = kv.x;
            Ks[r][col + 1] = kv.y;
            Ks[r][col + 2] = kv.z;
            Ks[r][col + 3] = kv.w;
            float4 vv = *(const float4*)(Vg + (size_t)(k0 + r) * HDIM + col);
            Vs[r][col + 0] = vv.x;
            Vs[r][col + 1] = vv.y;
            Vs[r][col + 2] = vv.z;
            Vs[r][col + 3] = vv.w;
        }
        __syncthreads();

        float sacc[4][2] = {};
#pragma unroll
        for (int d = 0; d < 64; d++) {
            float qf[4], kf[2];
#pragma unroll
            for (int i = 0; i < 4; i++) qf[i] = Qs[ty * 4 + i][d];
            kf[0] = Ks[tx * 2 + 0][d];
            kf[1] = Ks[tx * 2 + 1][d];
#pragma unroll
            for (int i = 0; i < 4; i++) {
                sacc[i][0] += qf[i] * kf[0];
                sacc[i][1] += qf[i] * kf[1];
            }
        }

#pragma unroll
        for (int i = 0; i < 4; i++)
#pragma unroll
            for (int j = 0; j < 2; j++) {
                const int q = q0 + ty * 4 + i;
                const int k = k0 + tx * 2 + j;
                if (k > q) sacc[i][j] = -1e30f;
            }

#pragma unroll
        for (int i = 0; i < 4; i++) {
            float mx = fmaxf(sacc[i][0], sacc[i][1]);
#pragma unroll
            for (int off = 8; off >= 1; off >>= 1)
                mx = fmaxf(mx, __shfl_xor_sync(0xffffffffu, mx, off));
            const float mnew = fmaxf(mrow[i], mx);
            const float p0 = __expf(sacc[i][0] - mnew);
            const float p1 = __expf(sacc[i][1] - mnew);
            float rs = p0 + p1;
#pragma unroll
            for (int off = 8; off >= 1; off >>= 1)
                rs += __shfl_xor_sync(0xffffffffu, rs, off);
            const float corr = __expf(mrow[i] - mnew);
            lrow[i] = lrow[i] * corr + rs;
            mrow[i] = mnew;
#pragma unroll
            for (int j = 0; j < 4; j++) o[i][j] *= corr;
            Ps[ty * 4 + i][tx * 2 + 0] = p0;
            Ps[ty * 4 + i][tx * 2 + 1] = p1;
        }
        __syncthreads();

#pragma unroll
        for (int k = 0; k < 32; k++) {
            float pf[4], vf[4];
#pragma unroll
            for (int i = 0; i < 4; i++) pf[i] = Ps[ty * 4 + i][k];
#pragma unroll
            for (int j = 0; j < 4; j++) vf[j] = Vs[k][tx * 4 + j];
#pragma unroll
            for (int i = 0; i < 4; i++)
#pragma unroll
                for (int j = 0; j < 4; j++)
                    o[i][j] += pf[i] * vf[j];
        }
        __syncthreads();
    }

    const int b = bh >> 4;
    const int h = bh & 15;
#pragma unroll
    for (int i = 0; i < 4; i++) {
        const float inv = 1.0f / lrow[i];
        const int t = q0 + ty * 4 + i;
        float4 v;
        v.x = o[i][0] * inv;
        v.y = o[i][1] * inv;
        v.z = o[i][2] * inv;
        v.w = o[i][3] * inv;
        *(float4*)(g_Y + (size_t)(b * TSEQ + t) * CDIM + h * HDIM + tx * 4) = v;
    }
}

// ---------------------------------------------------------------------------
extern "C" void kernel_launch(void* const* d_in, const int* in_sizes, int n_in,
                              void* d_out, int out_size)
{
    const float* x      = (const float*)d_in[0];
    const float* w_qkv  = (const float*)d_in[1];
    const float* b_qkv  = (const float*)d_in[2];
    const float* w_proj = (const float*)d_in[3];
    const float* b_proj = (const float*)d_in[4];
    float* out = (float*)d_out;

    qkv_gemm128<<<dim3(NQKV / 128, MROWS / 128), 256>>>(x, w_qkv, b_qkv);
    attn_kernel<<<dim3(TSEQ / 64, BATCH * NHEADS), 256>>>();
    proj_gemm128<<<dim3(CDIM / 128, MROWS / 128), 256>>>(w_proj, b_proj, out);
}

// round 5
// speedup vs baseline: 1.3461x; 1.1349x over previous
#include <cuda_runtime.h>

// Problem constants
#define BATCH   4
#define TSEQ    2048
#define CDIM    1024
#define NHEADS  16
#define HDIM    64
#define MROWS   (BATCH * TSEQ)     // 8192
#define NQKV    (3 * CDIM)         // 3072

// Scratch (allocation-free rule: __device__ globals)
__device__ float g_Q[(size_t)BATCH * NHEADS * TSEQ * HDIM];   // (B,H,T,Dh)
__device__ float g_K[(size_t)BATCH * NHEADS * TSEQ * HDIM];
__device__ float g_V[(size_t)BATCH * NHEADS * TSEQ * HDIM];
__device__ float g_Y[(size_t)MROWS * CDIM];                    // (B,T,C)

// ---------------------------------------------------------------------------
// Kernel 1: qkv = x @ w_qkv + b_qkv, scattered head-major. (unchanged R3)
// ---------------------------------------------------------------------------
__global__ __launch_bounds__(256) void qkv_gemm128(
    const float* __restrict__ A,
    const float* __restrict__ B,
    const float* __restrict__ bias)
{
    __shared__ __align__(16) float As[8][132];
    __shared__ __align__(16) float Bs[8][128];

    const int tid  = threadIdx.x;
    const int row0 = blockIdx.y * 128;
    const int col0 = blockIdx.x * 128;

    const int w    = tid >> 5;
    const int wr   = w >> 1;
    const int wc   = w & 1;
    const int lane = tid & 31;
    const int lr   = lane >> 3;
    const int lc   = lane & 7;
    const int mrow = wr * 32 + lr * 4;
    const int ncol = wc * 64 + lc * 4;

    const int arow = tid >> 1;
    const int acol = (tid & 1) * 4;
    const int brow = tid >> 5;
    const int bcol = (tid & 31) * 4;

    const float* Ag = A + (size_t)(row0 + arow) * CDIM + acol;
    const float* Bg = B + (size_t)brow * NQKV + col0 + bcol;

    float4 a4 = *(const float4*)(Ag);
    float4 b4 = *(const float4*)(Bg);

    float acc[2][2][4][4] = {};

    for (int k0 = 0; k0 < CDIM; k0 += 8) {
        __syncthreads();
        As[acol + 0][arow] = a4.x;
        As[acol + 1][arow] = a4.y;
        As[acol + 2][arow] = a4.z;
        As[acol + 3][arow] = a4.w;
        *(float4*)(&Bs[brow][bcol]) = b4;
        __syncthreads();

        if (k0 + 8 < CDIM) {
            a4 = *(const float4*)(Ag + k0 + 8);
            b4 = *(const float4*)(Bg + (size_t)(k0 + 8) * NQKV);
        }

#pragma unroll
        for (int kk = 0; kk < 8; kk++) {
            float4 a0 = *(const float4*)(&As[kk][mrow]);
            float4 a1 = *(const float4*)(&As[kk][mrow + 16]);
            float4 b0 = *(const float4*)(&Bs[kk][ncol]);
            float4 b1 = *(const float4*)(&Bs[kk][ncol + 32]);
            float ar[2][4] = {{a0.x, a0.y, a0.z, a0.w}, {a1.x, a1.y, a1.z, a1.w}};
            float br[2][4] = {{b0.x, b0.y, b0.z, b0.w}, {b1.x, b1.y, b1.z, b1.w}};
#pragma unroll
            for (int im = 0; im < 2; im++)
#pragma unroll
                for (int i = 0; i < 4; i++)
#pragma unroll
                    for (int jm = 0; jm < 2; jm++)
#pragma unroll
                        for (int j = 0; j < 4; j++)
                            acc[im][jm][i][j] += ar[im][i] * br[jm][j];
        }
    }

    float bb[2][4];
#pragma unroll
    for (int jm = 0; jm < 2; jm++)
#pragma unroll
        for (int j = 0; j < 4; j++)
            bb[jm][j] = bias[col0 + ncol + jm * 32 + j];

#pragma unroll
    for (int im = 0; im < 2; im++) {
#pragma unroll
        for (int i = 0; i < 4; i++) {
            const int row = row0 + mrow + im * 16 + i;
#pragma unroll
            for (int jm = 0; jm < 2; jm++) {
                const int col = col0 + ncol + jm * 32;
                float4 v;
                v.x = acc[im][jm][i][0] + bb[jm][0];
                v.y = acc[im][jm][i][1] + bb[jm][1];
                v.z = acc[im][jm][i][2] + bb[jm][2];
                v.w = acc[im][jm][i][3] + bb[jm][3];
                const int s = col >> 10;
                const int h = (col & 1023) >> 6;
                const int d = col & 63;
                const int b = row >> 11;
                const int t = row & 2047;
                float* dst = (s == 0) ? g_Q : (s == 1) ? g_K : g_V;
                *(float4*)(dst + ((size_t)(b * NHEADS + h) * TSEQ + t) * HDIM + d) = v;
            }
        }
    }
}

// ---------------------------------------------------------------------------
// Kernel 3: out = Y @ w_proj + b_proj. (unchanged R3)
// ---------------------------------------------------------------------------
__global__ __launch_bounds__(256) void proj_gemm128(
    const float* __restrict__ B,
    const float* __restrict__ bias,
    float* __restrict__ C)
{
    __shared__ __align__(16) float As[8][132];
    __shared__ __align__(16) float Bs[8][128];

    const int tid  = threadIdx.x;
    const int row0 = blockIdx.y * 128;
    const int col0 = blockIdx.x * 128;

    const int w    = tid >> 5;
    const int wr   = w >> 1;
    const int wc   = w & 1;
    const int lane = tid & 31;
    const int lr   = lane >> 3;
    const int lc   = lane & 7;
    const int mrow = wr * 32 + lr * 4;
    const int ncol = wc * 64 + lc * 4;

    const int arow = tid >> 1;
    const int acol = (tid & 1) * 4;
    const int brow = tid >> 5;
    const int bcol = (tid & 31) * 4;

    const float* Ag = g_Y + (size_t)(row0 + arow) * CDIM + acol;
    const float* Bg = B + (size_t)brow * CDIM + col0 + bcol;

    float4 a4 = *(const float4*)(Ag);
    float4 b4 = *(const float4*)(Bg);

    float acc[2][2][4][4] = {};

    for (int k0 = 0; k0 < CDIM; k0 += 8) {
        __syncthreads();
        As[acol + 0][arow] = a4.x;
        As[acol + 1][arow] = a4.y;
        As[acol + 2][arow] = a4.z;
        As[acol + 3][arow] = a4.w;
        *(float4*)(&Bs[brow][bcol]) = b4;
        __syncthreads();

        if (k0 + 8 < CDIM) {
            a4 = *(const float4*)(Ag + k0 + 8);
            b4 = *(const float4*)(Bg + (size_t)(k0 + 8) * CDIM);
        }

#pragma unroll
        for (int kk = 0; kk < 8; kk++) {
            float4 a0 = *(const float4*)(&As[kk][mrow]);
            float4 a1 = *(const float4*)(&As[kk][mrow + 16]);
            float4 b0 = *(const float4*)(&Bs[kk][ncol]);
            float4 b1 = *(const float4*)(&Bs[kk][ncol + 32]);
            float ar[2][4] = {{a0.x, a0.y, a0.z, a0.w}, {a1.x, a1.y, a1.z, a1.w}};
            float br[2][4] = {{b0.x, b0.y, b0.z, b0.w}, {b1.x, b1.y, b1.z, b1.w}};
#pragma unroll
            for (int im = 0; im < 2; im++)
#pragma unroll
                for (int i = 0; i < 4; i++)
#pragma unroll
                    for (int jm = 0; jm < 2; jm++)
#pragma unroll
                        for (int j = 0; j < 4; j++)
                            acc[im][jm][i][j] += ar[im][i] * br[jm][j];
        }
    }

    float bb[2][4];
#pragma unroll
    for (int jm = 0; jm < 2; jm++)
#pragma unroll
        for (int j = 0; j < 4; j++)
            bb[jm][j] = bias[col0 + ncol + jm * 32 + j];

#pragma unroll
    for (int im = 0; im < 2; im++) {
#pragma unroll
        for (int i = 0; i < 4; i++) {
            const int row = row0 + mrow + im * 16 + i;
#pragma unroll
            for (int jm = 0; jm < 2; jm++) {
                const int col = col0 + ncol + jm * 32;
                float4 v;
                v.x = acc[im][jm][i][0] + bb[jm][0];
                v.y = acc[im][jm][i][1] + bb[jm][1];
                v.z = acc[im][jm][i][2] + bb[jm][2];
                v.w = acc[im][jm][i][3] + bb[jm][3];
                *(float4*)(C + (size_t)row * CDIM + col) = v;
            }
        }
    }
}

// ---------------------------------------------------------------------------
// Kernel 2: causal flash attention, 128 queries/block, 64-key tiles.
// S GEMM 8x4 microtile (two 4-row quadrants), P stored transposed so the
// PV GEMM is all-float4. P^T aliases K^T (K dead after S GEMM).
// Dynamic smem: Qt[64][132] + union(Kt[64][68] / Pt[64][132]) + Vs[64][68].
// ---------------------------------------------------------------------------
#define QB        128
#define KT        64
#define QT_STRIDE 132
#define KT_STRIDE 68
#define VS_STRIDE 68
#define ATT_QT_OFF 0
#define ATT_U_OFF  (64 * QT_STRIDE)                 // 8448 floats
#define ATT_VS_OFF (ATT_U_OFF + 64 * QT_STRIDE)     // 16896 floats
#define ATT_SMEM_FLOATS (ATT_VS_OFF + 64 * VS_STRIDE)
#define ATT_SMEM_BYTES  (ATT_SMEM_FLOATS * 4)       // 84992

__global__ __launch_bounds__(256) void attn_kernel2()
{
    extern __shared__ __align__(16) float smem[];
    float* Qt = smem + ATT_QT_OFF;   // [d][q]   stride 132
    float* Kt = smem + ATT_U_OFF;    // [d][k]   stride 68  (phase 1)
    float* Pt = smem + ATT_U_OFF;    // [k][q]   stride 132 (phase 2, aliases Kt)
    float* Vs = smem + ATT_VS_OFF;   // [k][d]   stride 68

    const int tid = threadIdx.x;
    const int tx  = tid & 15;        // col group (16 x 4)
    const int ty  = tid >> 4;        // row group (16 x 4, two quadrants)
    const int bh  = blockIdx.y;
    const int q0  = blockIdx.x * QB;

    const float* Qg = g_Q + (size_t)bh * TSEQ * HDIM;
    const float* Kg = g_K + (size_t)bh * TSEQ * HDIM;
    const float* Vg = g_V + (size_t)bh * TSEQ * HDIM;

    const float scale = 0.125f;

    // Load Q tile transposed + pre-scaled: 2048 float4s, 8 per thread.
#pragma unroll
    for (int c = 0; c < 8; c++) {
        const int f  = c * 256 + tid;
        const int q  = f >> 4;
        const int dg = f & 15;
        float4 v = *(const float4*)(Qg + (size_t)(q0 + q) * HDIM + dg * 4);
        Qt[(dg * 4 + 0) * QT_STRIDE + q] = v.x * scale;
        Qt[(dg * 4 + 1) * QT_STRIDE + q] = v.y * scale;
        Qt[(dg * 4 + 2) * QT_STRIDE + q] = v.z * scale;
        Qt[(dg * 4 + 3) * QT_STRIDE + q] = v.w * scale;
    }

    float o[2][4][4] = {};
    float m[2][4] = {{-1e30f,-1e30f,-1e30f,-1e30f},{-1e30f,-1e30f,-1e30f,-1e30f}};
    float l[2][4] = {};

    const int nkt = 2 * blockIdx.x + 2;

    for (int kt = 0; kt < nkt; kt++) {
        const int k0 = kt * KT;
        __syncthreads();   // prior O GEMM done reading Pt/Vs

        // Load K transposed + V straight: 1024 float4s each, 4/thread.
#pragma unroll
        for (int c = 0; c < 4; c++) {
            const int f  = c * 256 + tid;
            const int kk = f >> 4;
            const int dg = f & 15;
            float4 kv = *(const float4*)(Kg + (size_t)(k0 + kk) * HDIM + dg * 4);
            Kt[(dg * 4 + 0) * KT_STRIDE + kk] = kv.x;
            Kt[(dg * 4 + 1) * KT_STRIDE + kk] = kv.y;
            Kt[(dg * 4 + 2) * KT_STRIDE + kk] = kv.z;
            Kt[(dg * 4 + 3) * KT_STRIDE + kk] = kv.w;
            *(float4*)(Vs + kk * VS_STRIDE + dg * 4) =
                *(const float4*)(Vg + (size_t)(k0 + kk) * HDIM + dg * 4);
        }
        __syncthreads();

        // S = Q K^T : 128x64x64, microtile 8(q) x 4(k)
        float sacc[2][4][4] = {};
#pragma unroll
        for (int d = 0; d < 64; d++) {
            float4 a0 = *(const float4*)(Qt + d * QT_STRIDE + ty * 4);
            float4 a1 = *(const float4*)(Qt + d * QT_STRIDE + ty * 4 + 64);
            float4 b  = *(const float4*)(Kt + d * KT_STRIDE + tx * 4);
            float ar[2][4] = {{a0.x, a0.y, a0.z, a0.w}, {a1.x, a1.y, a1.z, a1.w}};
            float br[4] = {b.x, b.y, b.z, b.w};
#pragma unroll
            for (int qd = 0; qd < 2; qd++)
#pragma unroll
                for (int i = 0; i < 4; i++)
#pragma unroll
                    for (int j = 0; j < 4; j++)
                        sacc[qd][i][j] += ar[qd][i] * br[j];
        }

        // Causal mask only on diagonal-overlapping tiles
        if (k0 + KT - 1 > q0) {
#pragma unroll
            for (int qd = 0; qd < 2; qd++)
#pragma unroll
                for (int i = 0; i < 4; i++) {
                    const int qrow = q0 + qd * 64 + ty * 4 + i;
#pragma unroll
                    for (int j = 0; j < 4; j++)
                        if (k0 + tx * 4 + j > qrow) sacc[qd][i][j] = -1e30f;
                }
        }

        // Online softmax (per row, reduce across 16 tx lanes = half warp)
#pragma unroll
        for (int qd = 0; qd < 2; qd++)
#pragma unroll
            for (int i = 0; i < 4; i++) {
                float mx = fmaxf(fmaxf(sacc[qd][i][0], sacc[qd][i][1]),
                                 fmaxf(sacc[qd][i][2], sacc[qd][i][3]));
#pragma unroll
                for (int off = 8; off >= 1; off >>= 1)
                    mx = fmaxf(mx, __shfl_xor_sync(0xffffffffu, mx, off));
                const float mnew = fmaxf(m[qd][i], mx);
                float rs = 0.f;
#pragma unroll
                for (int j = 0; j < 4; j++) {
                    const float p = __expf(sacc[qd][i][j] - mnew);
                    sacc[qd][i][j] = p;
                    rs += p;
                }
#pragma unroll
                for (int off = 8; off >= 1; off >>= 1)
                    rs += __shfl_xor_sync(0xffffffffu, rs, off);
                const float corr = __expf(m[qd][i] - mnew);
                l[qd][i] = l[qd][i] * corr + rs;
                m[qd][i] = mnew;
#pragma unroll
                for (int j = 0; j < 4; j++) o[qd][i][j] *= corr;
            }

        __syncthreads();   // all S-GEMM reads of Kt done before Pt overwrite

        // Write P transposed: Pt[k][q], float4 along q
#pragma unroll
        for (int qd = 0; qd < 2; qd++)
#pragma unroll
            for (int j = 0; j < 4; j++) {
                float4 v;
                v.x = sacc[qd][0][j];
                v.y = sacc[qd][1][j];
                v.z = sacc[qd][2][j];
                v.w = sacc[qd][3][j];
                *(float4*)(Pt + (tx * 4 + j) * QT_STRIDE + qd * 64 + ty * 4) = v;
            }
        __syncthreads();

        // O += P V : 128x64x64, microtile 8(q) x 4(d)
#pragma unroll
        for (int k = 0; k < 64; k++) {
            float4 p0 = *(const float4*)(Pt + k * QT_STRIDE + ty * 4);
            float4 p1 = *(const float4*)(Pt + k * QT_STRIDE + ty * 4 + 64);
            float4 v  = *(const float4*)(Vs + k * VS_STRIDE + tx * 4);
            float pr[2][4] = {{p0.x, p0.y, p0.z, p0.w}, {p1.x, p1.y, p1.z, p1.w}};
            float vr[4] = {v.x, v.y, v.z, v.w};
#pragma unroll
            for (int qd = 0; qd < 2; qd++)
#pragma unroll
                for (int i = 0; i < 4; i++)
#pragma unroll
                    for (int j = 0; j < 4; j++)
                        o[qd][i][j] += pr[qd][i] * vr[j];
        }
    }

    // Normalize and write to (B,T,C)
    const int b = bh >> 4;
    const int h = bh & 15;
#pragma unroll
    for (int qd = 0; qd < 2; qd++)
#pragma unroll
        for (int i = 0; i < 4; i++) {
            const float inv = 1.0f / l[qd][i];
            const int t = q0 + qd * 64 + ty * 4 + i;
            float4 v;
            v.x = o[qd][i][0] * inv;
            v.y = o[qd][i][1] * inv;
            v.z = o[qd][i][2] * inv;
            v.w = o[qd][i][3] * inv;
            *(float4*)(g_Y + (size_t)(b * TSEQ + t) * CDIM + h * HDIM + tx * 4) = v;
        }
}

// ---------------------------------------------------------------------------
extern "C" void kernel_launch(void* const* d_in, const int* in_sizes, int n_in,
                              void* d_out, int out_size)
{
    const float* x      = (const float*)d_in[0];
    const float* w_qkv  = (const float*)d_in[1];
    const float* b_qkv  = (const float*)d_in[2];
    const float* w_proj = (const float*)d_in[3];
    const float* b_proj = (const float*)d_in[4];
    float* out = (float*)d_out;

    cudaFuncSetAttribute(attn_kernel2,
                         cudaFuncAttributeMaxDynamicSharedMemorySize,
                         ATT_SMEM_BYTES);

    qkv_gemm128<<<dim3(NQKV / 128, MROWS / 128), 256>>>(x, w_qkv, b_qkv);
    attn_kernel2<<<dim3(TSEQ / QB, BATCH * NHEADS), 256, ATT_SMEM_BYTES>>>();
    proj_gemm128<<<dim3(CDIM / 128, MROWS / 128), 256>>>(w_proj, b_proj, out);
}

// round 13
// speedup vs baseline: 1.6630x; 1.2354x over previous
#include <cuda_runtime.h>
#include <cuda_bf16.h>
#include <cstdint>

// Problem constants
#define BATCH   4
#define TSEQ    2048
#define CDIM    1024
#define NHEADS  16
#define HDIM    64
#define MROWS   (BATCH * TSEQ)     // 8192
#define NQKV    (3 * CDIM)         // 3072
#define KEXP    (3 * CDIM)         // bf16x3 expanded reduction dim

// Scratch (allocation-free rule: __device__ globals)
__device__ float g_Q[(size_t)BATCH * NHEADS * TSEQ * HDIM];
__device__ float g_K[(size_t)BATCH * NHEADS * TSEQ * HDIM];
__device__ float g_V[(size_t)BATCH * NHEADS * TSEQ * HDIM];
__device__ float g_Y[(size_t)MROWS * CDIM];
// bf16x3-expanded operands
__device__ __nv_bfloat16 g_xe[(size_t)MROWS * KEXP];        // x expanded  [m][3K]
__device__ __nv_bfloat16 g_ye[(size_t)MROWS * KEXP];        // Y expanded  [m][3K]
__device__ __nv_bfloat16 g_wqkv_t[(size_t)NQKV * KEXP];     // w_qkv^T exp [n][3K]
__device__ __nv_bfloat16 g_wproj_t[(size_t)CDIM * KEXP];    // w_proj^T exp[n][3K]

// ---------------------------------------------------------------------------
// Warp-level MMA helpers (base sm_103-legal PTX: ldmatrix + mma.sync)
// ---------------------------------------------------------------------------
__device__ __forceinline__ uint32_t smem_u32(const void* p) {
    uint32_t a;
    asm("{ .reg .u64 t; cvta.to.shared.u64 t, %1; cvt.u32.u64 %0, t; }"
        : "=r"(a) : "l"(p));
    return a;
}

__device__ __forceinline__ void ldsm_x4(uint32_t& r0, uint32_t& r1,
                                        uint32_t& r2, uint32_t& r3, uint32_t addr) {
    asm volatile("ldmatrix.sync.aligned.m8n8.x4.shared.b16 {%0,%1,%2,%3}, [%4];"
                 : "=r"(r0), "=r"(r1), "=r"(r2), "=r"(r3) : "r"(addr));
}

__device__ __forceinline__ void ldsm_x2(uint32_t& r0, uint32_t& r1, uint32_t addr) {
    asm volatile("ldmatrix.sync.aligned.m8n8.x2.shared.b16 {%0,%1}, [%2];"
                 : "=r"(r0), "=r"(r1) : "r"(addr));
}

__device__ __forceinline__ void mma16816(float* c, const uint32_t* a,
                                         const uint32_t* b) {
    asm volatile(
        "mma.sync.aligned.m16n8k16.row.col.f32.bf16.bf16.f32 "
        "{%0,%1,%2,%3}, {%4,%5,%6,%7}, {%8,%9}, {%0,%1,%2,%3};"
        : "+f"(c[0]), "+f"(c[1]), "+f"(c[2]), "+f"(c[3])
        : "r"(a[0]), "r"(a[1]), "r"(a[2]), "r"(a[3]), "r"(b[0]), "r"(b[1]));
}

// ---------------------------------------------------------------------------
// Convert kernels (bf16x3 expansion)
// A blocks: [hi, hi, lo] ; B blocks: [hi, lo, hi]  =>  hi*hi + hi*lo + lo*hi
// ---------------------------------------------------------------------------
__global__ __launch_bounds__(256) void convert_act(
    const float* __restrict__ a, __nv_bfloat16* __restrict__ ae)
{
    const size_t idx = (size_t)blockIdx.x * 256 + threadIdx.x;
    const int m = (int)(idx >> 10);
    const int k = (int)(idx & 1023);
    const float v = a[idx];
    const __nv_bfloat16 hi = __float2bfloat16(v);
    const __nv_bfloat16 lo = __float2bfloat16(v - __bfloat162float(hi));
    const size_t base = (size_t)m * KEXP;
    ae[base + k]            = hi;
    ae[base + CDIM + k]     = hi;
    ae[base + 2 * CDIM + k] = lo;
}

__global__ __launch_bounds__(256) void convert_wt(
    const float* __restrict__ w, __nv_bfloat16* __restrict__ wt, const int Nw)
{
    __shared__ float t[32][33];
    const int k0 = blockIdx.x * 32;
    const int n0 = blockIdx.y * 32;
    const int tx = threadIdx.x & 31;
    const int ty = threadIdx.x >> 5;     // 0..7
#pragma unroll
    for (int i = 0; i < 4; i++)
        t[ty + i * 8][tx] = w[(size_t)(k0 + ty + i * 8) * Nw + n0 + tx];
    __syncthreads();
#pragma unroll
    for (int i = 0; i < 4; i++) {
        const int n = n0 + ty + i * 8;
        const int k = k0 + tx;
        const float v = t[tx][ty + i * 8];
        const __nv_bfloat16 hi = __float2bfloat16(v);
        const __nv_bfloat16 lo = __float2bfloat16(v - __bfloat162float(hi));
        const size_t base = (size_t)n * KEXP;
        wt[base + k]            = hi;
        wt[base + CDIM + k]     = lo;
        wt[base + 2 * CDIM + k] = hi;
    }
}

// ---------------------------------------------------------------------------
// HMMA GEMM: C[128x128] = Ae[128 x K'] * Be[n][K']^T (+bias), K' = 3072.
// 256 threads = 8 warps (2m x 4n), warp tile 64x32, mma.m16n8k16 bf16.
// smem tiles stride 40 bf16 (80B) -> ldmatrix conflict-free.
// ---------------------------------------------------------------------------
#define TSTRIDE 40
#define KC      32

__global__ __launch_bounds__(256) void mma_gemm(
    const __nv_bfloat16* __restrict__ Ae,   // [MROWS][KEXP]
    const __nv_bfloat16* __restrict__ Be,   // [N][KEXP]
    const float* __restrict__ bias,
    float* __restrict__ Cout,
    const int scatter)
{
    __shared__ __align__(16) __nv_bfloat16 As[128 * TSTRIDE];
    __shared__ __align__(16) __nv_bfloat16 Bs[128 * TSTRIDE];

    const int tid  = threadIdx.x;
    const int wid  = tid >> 5;
    const int lane = tid & 31;
    const int row0 = blockIdx.y * 128;
    const int col0 = blockIdx.x * 128;

    const int wr = wid >> 2;          // 0..1
    const int wc = wid & 3;           // 0..3
    const int m0 = wr * 64;
    const int n0 = wc * 32;

    // ldmatrix per-lane row/col offsets
    const int a_row = (lane & 7) + 8 * ((lane >> 3) & 1);
    const int a_col = 8 * (lane >> 4);
    const int b_row = lane & 7;
    const int b_col = 8 * ((lane >> 3) & 1);

    const uint32_t sA = smem_u32(As);
    const uint32_t sB = smem_u32(Bs);

    // gmem loaders: rows tid>>2 and 64+(tid>>2), col group (tid&3)*8
    const int lrow = tid >> 2;            // 0..63
    const int lkg  = (tid & 3) * 8;       // 0,8,16,24

    const __nv_bfloat16* Ag = Ae + (size_t)row0 * KEXP;
    const __nv_bfloat16* Bg = Be + (size_t)col0 * KEXP;

    float acc[4][4][4] = {};   // [mtile][ntile][c0..c3]

    float4 a40 = *(const float4*)(Ag + (size_t)lrow * KEXP + lkg);
    float4 a41 = *(const float4*)(Ag + (size_t)(lrow + 64) * KEXP + lkg);
    float4 b40 = *(const float4*)(Bg + (size_t)lrow * KEXP + lkg);
    float4 b41 = *(const float4*)(Bg + (size_t)(lrow + 64) * KEXP + lkg);

    for (int k0 = 0; k0 < KEXP; k0 += KC) {
        __syncthreads();
        *(float4*)(As + lrow * TSTRIDE + lkg)        = a40;
        *(float4*)(As + (lrow + 64) * TSTRIDE + lkg) = a41;
        *(float4*)(Bs + lrow * TSTRIDE + lkg)        = b40;
        *(float4*)(Bs + (lrow + 64) * TSTRIDE + lkg) = b41;
        __syncthreads();

        if (k0 + KC < KEXP) {
            a40 = *(const float4*)(Ag + (size_t)lrow * KEXP + k0 + KC + lkg);
            a41 = *(const float4*)(Ag + (size_t)(lrow + 64) * KEXP + k0 + KC + lkg);
            b40 = *(const float4*)(Bg + (size_t)lrow * KEXP + k0 + KC + lkg);
            b41 = *(const float4*)(Bg + (size_t)(lrow + 64) * KEXP + k0 + KC + lkg);
        }

#pragma unroll
        for (int ks = 0; ks < 2; ks++) {
            const int kb = ks * 16;
            uint32_t af[4][4];
#pragma unroll
            for (int i = 0; i < 4; i++) {
                const uint32_t addr =
                    sA + (uint32_t)(((m0 + 16 * i + a_row) * TSTRIDE + kb + a_col) * 2);
                ldsm_x4(af[i][0], af[i][1], af[i][2], af[i][3], addr);
            }
            uint32_t bf[4][2];
#pragma unroll
            for (int j = 0; j < 4; j++) {
                const uint32_t addr =
                    sB + (uint32_t)(((n0 + 8 * j + b_row) * TSTRIDE + kb + b_col) * 2);
                ldsm_x2(bf[j][0], bf[j][1], addr);
            }
#pragma unroll
            for (int i = 0; i < 4; i++)
#pragma unroll
                for (int j = 0; j < 4; j++)
                    mma16816(acc[i][j], af[i], bf[j]);
        }
    }

    // Epilogue: fragment (g = lane>>2, tig = lane&3)
    const int g   = lane >> 2;
    const int tig = lane & 3;
#pragma unroll
    for (int i = 0; i < 4; i++) {
#pragma unroll
        for (int j = 0; j < 4; j++) {
            const int col = col0 + n0 + 8 * j + 2 * tig;
            const float bx = bias[col];
            const float by = bias[col + 1];
            const int r0 = row0 + m0 + 16 * i + g;
            const int r1 = r0 + 8;
            float2 v0 = make_float2(acc[i][j][0] + bx, acc[i][j][1] + by);
            float2 v1 = make_float2(acc[i][j][2] + bx, acc[i][j][3] + by);
            if (scatter) {
                const int s = col >> 10;
                const int h = (col & 1023) >> 6;
                const int d = col & 63;
                float* dst = (s == 0) ? g_Q : (s == 1) ? g_K : g_V;
                const int b0i = r0 >> 11, t0i = r0 & 2047;
                const int b1i = r1 >> 11, t1i = r1 & 2047;
                *(float2*)(dst + ((size_t)(b0i * NHEADS + h) * TSEQ + t0i) * HDIM + d) = v0;
                *(float2*)(dst + ((size_t)(b1i * NHEADS + h) * TSEQ + t1i) * HDIM + d) = v1;
            } else {
                *(float2*)(Cout + (size_t)r0 * CDIM + col) = v0;
                *(float2*)(Cout + (size_t)r1 * CDIM + col) = v1;
            }
        }
    }
}

// ---------------------------------------------------------------------------
// Kernel 2: causal flash attention (unchanged from R5, passing).
// ---------------------------------------------------------------------------
#define QB        128
#define KT        64
#define QT_STRIDE 132
#define KT_STRIDE 68
#define VS_STRIDE 68
#define ATT_QT_OFF 0
#define ATT_U_OFF  (64 * QT_STRIDE)
#define ATT_VS_OFF (ATT_U_OFF + 64 * QT_STRIDE)
#define ATT_SMEM_FLOATS (ATT_VS_OFF + 64 * VS_STRIDE)
#define ATT_SMEM_BYTES  (ATT_SMEM_FLOATS * 4)

__global__ __launch_bounds__(256) void attn_kernel2()
{
    extern __shared__ __align__(16) float asmem[];
    float* Qt = asmem + ATT_QT_OFF;
    float* Kt = asmem + ATT_U_OFF;
    float* Pt = asmem + ATT_U_OFF;
    float* Vs = asmem + ATT_VS_OFF;

    const int tid = threadIdx.x;
    const int tx  = tid & 15;
    const int ty  = tid >> 4;
    const int bh  = blockIdx.y;
    const int q0  = blockIdx.x * QB;

    const float* Qg = g_Q + (size_t)bh * TSEQ * HDIM;
    const float* Kg = g_K + (size_t)bh * TSEQ * HDIM;
    const float* Vg = g_V + (size_t)bh * TSEQ * HDIM;

    const float scale = 0.125f;

#pragma unroll
    for (int c = 0; c < 8; c++) {
        const int f  = c * 256 + tid;
        const int q  = f >> 4;
        const int dg = f & 15;
        float4 v = *(const float4*)(Qg + (size_t)(q0 + q) * HDIM + dg * 4);
        Qt[(dg * 4 + 0) * QT_STRIDE + q] = v.x * scale;
        Qt[(dg * 4 + 1) * QT_STRIDE + q] = v.y * scale;
        Qt[(dg * 4 + 2) * QT_STRIDE + q] = v.z * scale;
        Qt[(dg * 4 + 3) * QT_STRIDE + q] = v.w * scale;
    }

    float o[2][4][4] = {};
    float m[2][4] = {{-1e30f,-1e30f,-1e30f,-1e30f},{-1e30f,-1e30f,-1e30f,-1e30f}};
    float l[2][4] = {};

    const int nkt = 2 * blockIdx.x + 2;

    for (int kt = 0; kt < nkt; kt++) {
        const int k0 = kt * KT;
        __syncthreads();

#pragma unroll
        for (int c = 0; c < 4; c++) {
            const int f  = c * 256 + tid;
            const int kk = f >> 4;
            const int dg = f & 15;
            float4 kv = *(const float4*)(Kg + (size_t)(k0 + kk) * HDIM + dg * 4);
            Kt[(dg * 4 + 0) * KT_STRIDE + kk] = kv.x;
            Kt[(dg * 4 + 1) * KT_STRIDE + kk] = kv.y;
            Kt[(dg * 4 + 2) * KT_STRIDE + kk] = kv.z;
            Kt[(dg * 4 + 3) * KT_STRIDE + kk] = kv.w;
            *(float4*)(Vs + kk * VS_STRIDE + dg * 4) =
                *(const float4*)(Vg + (size_t)(k0 + kk) * HDIM + dg * 4);
        }
        __syncthreads();

        float sacc[2][4][4] = {};
#pragma unroll
        for (int d = 0; d < 64; d++) {
            float4 a0 = *(const float4*)(Qt + d * QT_STRIDE + ty * 4);
            float4 a1 = *(const float4*)(Qt + d * QT_STRIDE + ty * 4 + 64);
            float4 bv = *(const float4*)(Kt + d * KT_STRIDE + tx * 4);
            float ar[2][4] = {{a0.x, a0.y, a0.z, a0.w}, {a1.x, a1.y, a1.z, a1.w}};
            float br[4] = {bv.x, bv.y, bv.z, bv.w};
#pragma unroll
            for (int qd = 0; qd < 2; qd++)
#pragma unroll
                for (int i = 0; i < 4; i++)
#pragma unroll
                    for (int j = 0; j < 4; j++)
                        sacc[qd][i][j] += ar[qd][i] * br[j];
        }

        if (k0 + KT - 1 > q0) {
#pragma unroll
            for (int qd = 0; qd < 2; qd++)
#pragma unroll
                for (int i = 0; i < 4; i++) {
                    const int qrow = q0 + qd * 64 + ty * 4 + i;
#pragma unroll
                    for (int j = 0; j < 4; j++)
                        if (k0 + tx * 4 + j > qrow) sacc[qd][i][j] = -1e30f;
                }
        }

#pragma unroll
        for (int qd = 0; qd < 2; qd++)
#pragma unroll
            for (int i = 0; i < 4; i++) {
                float mx = fmaxf(fmaxf(sacc[qd][i][0], sacc[qd][i][1]),
                                 fmaxf(sacc[qd][i][2], sacc[qd][i][3]));
#pragma unroll
                for (int off = 8; off >= 1; off >>= 1)
                    mx = fmaxf(mx, __shfl_xor_sync(0xffffffffu, mx, off));
                const float mnew = fmaxf(m[qd][i], mx);
                float rs = 0.f;
#pragma unroll
                for (int j = 0; j < 4; j++) {
                    const float p = __expf(sacc[qd][i][j] - mnew);
                    sacc[qd][i][j] = p;
                    rs += p;
                }
#pragma unroll
                for (int off = 8; off >= 1; off >>= 1)
                    rs += __shfl_xor_sync(0xffffffffu, rs, off);
                const float corr = __expf(m[qd][i] - mnew);
                l[qd][i] = l[qd][i] * corr + rs;
                m[qd][i] = mnew;
#pragma unroll
                for (int j = 0; j < 4; j++) o[qd][i][j] *= corr;
            }

        __syncthreads();

#pragma unroll
        for (int qd = 0; qd < 2; qd++)
#pragma unroll
            for (int j = 0; j < 4; j++) {
                float4 v;
                v.x = sacc[qd][0][j];
                v.y = sacc[qd][1][j];
                v.z = sacc[qd][2][j];
                v.w = sacc[qd][3][j];
                *(float4*)(Pt + (tx * 4 + j) * QT_STRIDE + qd * 64 + ty * 4) = v;
            }
        __syncthreads();

#pragma unroll
        for (int k = 0; k < 64; k++) {
            float4 p0 = *(const float4*)(Pt + k * QT_STRIDE + ty * 4);
            float4 p1 = *(const float4*)(Pt + k * QT_STRIDE + ty * 4 + 64);
            float4 v  = *(const float4*)(Vs + k * VS_STRIDE + tx * 4);
            float pr[2][4] = {{p0.x, p0.y, p0.z, p0.w}, {p1.x, p1.y, p1.z, p1.w}};
            float vr[4] = {v.x, v.y, v.z, v.w};
#pragma unroll
            for (int qd = 0; qd < 2; qd++)
#pragma unroll
                for (int i = 0; i < 4; i++)
#pragma unroll
                    for (int j = 0; j < 4; j++)
                        o[qd][i][j] += pr[qd][i] * vr[j];
        }
    }

    const int b = bh >> 4;
    const int h = bh & 15;
#pragma unroll
    for (int qd = 0; qd < 2; qd++)
#pragma unroll
        for (int i = 0; i < 4; i++) {
            const float inv = 1.0f / l[qd][i];
            const int t = q0 + qd * 64 + ty * 4 + i;
            float4 v;
            v.x = o[qd][i][0] * inv;
            v.y = o[qd][i][1] * inv;
            v.z = o[qd][i][2] * inv;
            v.w = o[qd][i][3] * inv;
            *(float4*)(g_Y + (size_t)(b * TSEQ + t) * CDIM + h * HDIM + tx * 4) = v;
        }
}

// ---------------------------------------------------------------------------
extern "C" void kernel_launch(void* const* d_in, const int* in_sizes, int n_in,
                              void* d_out, int out_size)
{
    const float* x      = (const float*)d_in[0];
    const float* w_qkv  = (const float*)d_in[1];
    const float* b_qkv  = (const float*)d_in[2];
    const float* w_proj = (const float*)d_in[3];
    const float* b_proj = (const float*)d_in[4];
    float* out = (float*)d_out;

    // CRITICAL: resolve true DEVICE addresses of __device__ globals that are
    // passed as kernel arguments. Using the symbols directly in host code
    // passes the host shadow address (silently "works" via ATS on GB300 but
    // reads/writes the wrong memory — root cause of the R2/R12 zero-output).
    void *p_xe = nullptr, *p_ye = nullptr, *p_wq = nullptr, *p_wp = nullptr,
         *p_Y = nullptr;
    cudaGetSymbolAddress(&p_xe, g_xe);
    cudaGetSymbolAddress(&p_ye, g_ye);
    cudaGetSymbolAddress(&p_wq, g_wqkv_t);
    cudaGetSymbolAddress(&p_wp, g_wproj_t);
    cudaGetSymbolAddress(&p_Y,  g_Y);
    __nv_bfloat16* xe = (__nv_bfloat16*)p_xe;
    __nv_bfloat16* ye = (__nv_bfloat16*)p_ye;
    __nv_bfloat16* wq = (__nv_bfloat16*)p_wq;
    __nv_bfloat16* wp = (__nv_bfloat16*)p_wp;
    float* Yd = (float*)p_Y;

    cudaFuncSetAttribute(attn_kernel2,
                         cudaFuncAttributeMaxDynamicSharedMemorySize,
                         ATT_SMEM_BYTES);

    // bf16x3 expansion
    convert_act<<<(MROWS * CDIM) / 256, 256>>>(x, xe);
    convert_wt<<<dim3(CDIM / 32, NQKV / 32), 256>>>(w_qkv, wq, NQKV);
    convert_wt<<<dim3(CDIM / 32, CDIM / 32), 256>>>(w_proj, wp, CDIM);

    mma_gemm<<<dim3(NQKV / 128, MROWS / 128), 256>>>(xe, wq, b_qkv, nullptr, 1);
    attn_kernel2<<<dim3(TSEQ / QB, BATCH * NHEADS), 256, ATT_SMEM_BYTES>>>();
    convert_act<<<(MROWS * CDIM) / 256, 256>>>(Yd, ye);
    mma_gemm<<<dim3(CDIM / 128, MROWS / 128), 256>>>(ye, wp, b_proj, out, 0);
}

// round 15
// speedup vs baseline: 2.2205x; 1.3352x over previous
#include <cuda_runtime.h>
#include <cuda_bf16.h>
#include <cstdint>

// Problem constants
#define BATCH   4
#define TSEQ    2048
#define CDIM    1024
#define NHEADS  16
#define HDIM    64
#define MROWS   (BATCH * TSEQ)     // 8192
#define NQKV    (3 * CDIM)         // 3072
#define KEXP    (3 * CDIM)         // bf16x3 expanded reduction dim

// Scratch (allocation-free rule: __device__ globals)
__device__ float g_Q[(size_t)BATCH * NHEADS * TSEQ * HDIM];
__device__ float g_K[(size_t)BATCH * NHEADS * TSEQ * HDIM];
__device__ float g_V[(size_t)BATCH * NHEADS * TSEQ * HDIM];
__device__ float g_Y[(size_t)MROWS * CDIM];
// bf16x3-expanded operands
__device__ __nv_bfloat16 g_xe[(size_t)MROWS * KEXP];
__device__ __nv_bfloat16 g_ye[(size_t)MROWS * KEXP];
__device__ __nv_bfloat16 g_wqkv_t[(size_t)NQKV * KEXP];
__device__ __nv_bfloat16 g_wproj_t[(size_t)CDIM * KEXP];

// ---------------------------------------------------------------------------
// Warp-level MMA helpers (base sm_103-legal PTX: ldmatrix + mma.sync)
// ---------------------------------------------------------------------------
__device__ __forceinline__ uint32_t smem_u32(const void* p) {
    uint32_t a;
    asm("{ .reg .u64 t; cvta.to.shared.u64 t, %1; cvt.u32.u64 %0, t; }"
        : "=r"(a) : "l"(p));
    return a;
}

__device__ __forceinline__ void ldsm_x4(uint32_t& r0, uint32_t& r1,
                                        uint32_t& r2, uint32_t& r3, uint32_t addr) {
    asm volatile("ldmatrix.sync.aligned.m8n8.x4.shared.b16 {%0,%1,%2,%3}, [%4];"
                 : "=r"(r0), "=r"(r1), "=r"(r2), "=r"(r3) : "r"(addr));
}

__device__ __forceinline__ void ldsm_x2(uint32_t& r0, uint32_t& r1, uint32_t addr) {
    asm volatile("ldmatrix.sync.aligned.m8n8.x2.shared.b16 {%0,%1}, [%2];"
                 : "=r"(r0), "=r"(r1) : "r"(addr));
}

__device__ __forceinline__ void mma16816(float* c, const uint32_t* a,
                                         const uint32_t* b) {
    asm volatile(
        "mma.sync.aligned.m16n8k16.row.col.f32.bf16.bf16.f32 "
        "{%0,%1,%2,%3}, {%4,%5,%6,%7}, {%8,%9}, {%0,%1,%2,%3};"
        : "+f"(c[0]), "+f"(c[1]), "+f"(c[2]), "+f"(c[3])
        : "r"(a[0]), "r"(a[1]), "r"(a[2]), "r"(a[3]), "r"(b[0]), "r"(b[1]));
}

__device__ __forceinline__ void bsplit(float v, __nv_bfloat16& h, __nv_bfloat16& l) {
    h = __float2bfloat16(v);
    l = __float2bfloat16(v - __bfloat162float(h));
}

// ---------------------------------------------------------------------------
// Convert kernels (bf16x3 expansion)
// ---------------------------------------------------------------------------
__global__ __launch_bounds__(256) void convert_act(
    const float* __restrict__ a, __nv_bfloat16* __restrict__ ae)
{
    const size_t idx = (size_t)blockIdx.x * 256 + threadIdx.x;
    const int m = (int)(idx >> 10);
    const int k = (int)(idx & 1023);
    const float v = a[idx];
    __nv_bfloat16 hi, lo;
    bsplit(v, hi, lo);
    const size_t base = (size_t)m * KEXP;
    ae[base + k]            = hi;
    ae[base + CDIM + k]     = hi;
    ae[base + 2 * CDIM + k] = lo;
}

__global__ __launch_bounds__(256) void convert_wt(
    const float* __restrict__ w, __nv_bfloat16* __restrict__ wt, const int Nw)
{
    __shared__ float t[32][33];
    const int k0 = blockIdx.x * 32;
    const int n0 = blockIdx.y * 32;
    const int tx = threadIdx.x & 31;
    const int ty = threadIdx.x >> 5;
#pragma unroll
    for (int i = 0; i < 4; i++)
        t[ty + i * 8][tx] = w[(size_t)(k0 + ty + i * 8) * Nw + n0 + tx];
    __syncthreads();
#pragma unroll
    for (int i = 0; i < 4; i++) {
        const int n = n0 + ty + i * 8;
        const int k = k0 + tx;
        __nv_bfloat16 hi, lo;
        bsplit(t[tx][ty + i * 8], hi, lo);
        const size_t base = (size_t)n * KEXP;
        wt[base + k]            = hi;
        wt[base + CDIM + k]     = lo;
        wt[base + 2 * CDIM + k] = hi;
    }
}

// ---------------------------------------------------------------------------
// HMMA GEMM (unchanged from R13, passing)
// ---------------------------------------------------------------------------
#define TSTRIDE 40
#define KC      32

__global__ __launch_bounds__(256) void mma_gemm(
    const __nv_bfloat16* __restrict__ Ae,
    const __nv_bfloat16* __restrict__ Be,
    const float* __restrict__ bias,
    float* __restrict__ Cout,
    const int scatter)
{
    __shared__ __align__(16) __nv_bfloat16 As[128 * TSTRIDE];
    __shared__ __align__(16) __nv_bfloat16 Bs[128 * TSTRIDE];

    const int tid  = threadIdx.x;
    const int wid  = tid >> 5;
    const int lane = tid & 31;
    const int row0 = blockIdx.y * 128;
    const int col0 = blockIdx.x * 128;

    const int wr = wid >> 2;
    const int wc = wid & 3;
    const int m0 = wr * 64;
    const int n0 = wc * 32;

    const int a_row = (lane & 7) + 8 * ((lane >> 3) & 1);
    const int a_col = 8 * (lane >> 4);
    const int b_row = lane & 7;
    const int b_col = 8 * ((lane >> 3) & 1);

    const uint32_t sA = smem_u32(As);
    const uint32_t sB = smem_u32(Bs);

    const int lrow = tid >> 2;
    const int lkg  = (tid & 3) * 8;

    const __nv_bfloat16* Ag = Ae + (size_t)row0 * KEXP;
    const __nv_bfloat16* Bg = Be + (size_t)col0 * KEXP;

    float acc[4][4][4] = {};

    float4 a40 = *(const float4*)(Ag + (size_t)lrow * KEXP + lkg);
    float4 a41 = *(const float4*)(Ag + (size_t)(lrow + 64) * KEXP + lkg);
    float4 b40 = *(const float4*)(Bg + (size_t)lrow * KEXP + lkg);
    float4 b41 = *(const float4*)(Bg + (size_t)(lrow + 64) * KEXP + lkg);

    for (int k0 = 0; k0 < KEXP; k0 += KC) {
        __syncthreads();
        *(float4*)(As + lrow * TSTRIDE + lkg)        = a40;
        *(float4*)(As + (lrow + 64) * TSTRIDE + lkg) = a41;
        *(float4*)(Bs + lrow * TSTRIDE + lkg)        = b40;
        *(float4*)(Bs + (lrow + 64) * TSTRIDE + lkg) = b41;
        __syncthreads();

        if (k0 + KC < KEXP) {
            a40 = *(const float4*)(Ag + (size_t)lrow * KEXP + k0 + KC + lkg);
            a41 = *(const float4*)(Ag + (size_t)(lrow + 64) * KEXP + k0 + KC + lkg);
            b40 = *(const float4*)(Bg + (size_t)lrow * KEXP + k0 + KC + lkg);
            b41 = *(const float4*)(Bg + (size_t)(lrow + 64) * KEXP + k0 + KC + lkg);
        }

#pragma unroll
        for (int ks = 0; ks < 2; ks++) {
            const int kb = ks * 16;
            uint32_t af[4][4];
#pragma unroll
            for (int i = 0; i < 4; i++) {
                const uint32_t addr =
                    sA + (uint32_t)(((m0 + 16 * i + a_row) * TSTRIDE + kb + a_col) * 2);
                ldsm_x4(af[i][0], af[i][1], af[i][2], af[i][3], addr);
            }
            uint32_t bf[4][2];
#pragma unroll
            for (int j = 0; j < 4; j++) {
                const uint32_t addr =
                    sB + (uint32_t)(((n0 + 8 * j + b_row) * TSTRIDE + kb + b_col) * 2);
                ldsm_x2(bf[j][0], bf[j][1], addr);
            }
#pragma unroll
            for (int i = 0; i < 4; i++)
#pragma unroll
                for (int j = 0; j < 4; j++)
                    mma16816(acc[i][j], af[i], bf[j]);
        }
    }

    const int g   = lane >> 2;
    const int tig = lane & 3;
#pragma unroll
    for (int i = 0; i < 4; i++) {
#pragma unroll
        for (int j = 0; j < 4; j++) {
            const int col = col0 + n0 + 8 * j + 2 * tig;
            const float bx = bias[col];
            const float by = bias[col + 1];
            const int r0 = row0 + m0 + 16 * i + g;
            const int r1 = r0 + 8;
            float2 v0 = make_float2(acc[i][j][0] + bx, acc[i][j][1] + by);
            float2 v1 = make_float2(acc[i][j][2] + bx, acc[i][j][3] + by);
            if (scatter) {
                const int s = col >> 10;
                const int h = (col & 1023) >> 6;
                const int d = col & 63;
                float* dst = (s == 0) ? g_Q : (s == 1) ? g_K : g_V;
                const int b0i = r0 >> 11, t0i = r0 & 2047;
                const int b1i = r1 >> 11, t1i = r1 & 2047;
                *(float2*)(dst + ((size_t)(b0i * NHEADS + h) * TSEQ + t0i) * HDIM + d) = v0;
                *(float2*)(dst + ((size_t)(b1i * NHEADS + h) * TSEQ + t1i) * HDIM + d) = v1;
            } else {
                *(float2*)(Cout + (size_t)r0 * CDIM + col) = v0;
                *(float2*)(Cout + (size_t)r1 * CDIM + col) = v1;
            }
        }
    }
}

// ---------------------------------------------------------------------------
// HMMA causal flash attention.
// 128 q/block, 64-key tiles, bf16x3 split (k'=192), 8 warps in 8m x 1n:
// each warp owns 16 COMPLETE q rows (full 64-key span) -> softmax is
// warp-private and P normalization is consistent (fixes R14 bug).
// smem (bf16, stride 200): Qe[128] | U=max(Ke[64],Pt[128]) | Vt[64 d rows]
// ---------------------------------------------------------------------------
#define AQ_STR 200
#define AKT    64
#define A_SMEM_BF16 (320 * AQ_STR)
#define A_SMEM_BYTES (A_SMEM_BF16 * 2)        // 128000 B

__global__ __launch_bounds__(256) void attn_mma()
{
    extern __shared__ __align__(16) __nv_bfloat16 smx[];
    __nv_bfloat16* Qe = smx;                  // [128][200]  [qh|qh|ql]
    __nv_bfloat16* Ke = smx + 128 * AQ_STR;   // [64][200]   [kh|kl|kh]
    __nv_bfloat16* Pt = smx + 128 * AQ_STR;   // [128][200]  [ph|ph|pl] (aliases Ke)
    __nv_bfloat16* Vt = smx + 256 * AQ_STR;   // [64 d][200] [vh|vl|vh]

    const int tid  = threadIdx.x;
    const int wid  = tid >> 5;
    const int lane = tid & 31;
    const int m0w  = wid * 16;          // 16 complete rows per warp

    const int a_row = (lane & 7) + 8 * ((lane >> 3) & 1);
    const int a_col = 8 * (lane >> 4);
    const int b_row = lane & 7;
    const int b_col = 8 * ((lane >> 3) & 1);
    const int g     = lane >> 2;
    const int tig   = lane & 3;

    const uint32_t sQ = smem_u32(Qe);
    const uint32_t sK = smem_u32(Ke);
    const uint32_t sP = smem_u32(Pt);
    const uint32_t sV = smem_u32(Vt);

    const int bh = blockIdx.y;
    const int q0 = blockIdx.x * 128;

    const float* Qg = g_Q + (size_t)bh * TSEQ * HDIM;
    const float* Kg = g_K + (size_t)bh * TSEQ * HDIM;
    const float* Vg = g_V + (size_t)bh * TSEQ * HDIM;

    const float scale = 0.125f;

    // Load Q (pre-scaled, split): 2048 float4, 8 per thread
#pragma unroll
    for (int c = 0; c < 8; c++) {
        const int f  = c * 256 + tid;
        const int q  = f >> 4;
        const int dg = (f & 15) * 4;
        float4 v = *(const float4*)(Qg + (size_t)(q0 + q) * HDIM + dg);
        float vv[4] = {v.x, v.y, v.z, v.w};
#pragma unroll
        for (int e = 0; e < 4; e++) {
            __nv_bfloat16 h, l;
            bsplit(vv[e] * scale, h, l);
            Qe[q * AQ_STR + dg + e]       = h;
            Qe[q * AQ_STR + 64 + dg + e]  = h;
            Qe[q * AQ_STR + 128 + dg + e] = l;
        }
    }

    float oacc[8][4] = {};
    float mrow[2] = {-1e30f, -1e30f};
    float lrow[2] = {};

    const int nkt = 2 * blockIdx.x + 2;

    for (int kt = 0; kt < nkt; kt++) {
        const int k0 = kt * AKT;
        __syncthreads();   // prior PV reads of Pt/Vt done before overwrite

        // Load K (expanded, row=key) and V (transposed+expanded, row=d)
#pragma unroll
        for (int c = 0; c < 4; c++) {
            const int f  = c * 256 + tid;
            const int kk = f >> 4;
            const int dg = (f & 15) * 4;
            float4 kv = *(const float4*)(Kg + (size_t)(k0 + kk) * HDIM + dg);
            float kvv[4] = {kv.x, kv.y, kv.z, kv.w};
#pragma unroll
            for (int e = 0; e < 4; e++) {
                __nv_bfloat16 h, l;
                bsplit(kvv[e], h, l);
                Ke[kk * AQ_STR + dg + e]       = h;
                Ke[kk * AQ_STR + 64 + dg + e]  = l;
                Ke[kk * AQ_STR + 128 + dg + e] = h;
            }
            float4 vv4 = *(const float4*)(Vg + (size_t)(k0 + kk) * HDIM + dg);
            float vvv[4] = {vv4.x, vv4.y, vv4.z, vv4.w};
#pragma unroll
            for (int e = 0; e < 4; e++) {
                __nv_bfloat16 h, l;
                bsplit(vvv[e], h, l);
                Vt[(dg + e) * AQ_STR + kk]       = h;
                Vt[(dg + e) * AQ_STR + 64 + kk]  = l;
                Vt[(dg + e) * AQ_STR + 128 + kk] = h;
            }
        }
        __syncthreads();

        // S = Q' K'^T : warp tile 16(q) x 64(key) x 192
        float sacc[8][4] = {};
#pragma unroll
        for (int ks = 0; ks < 12; ks++) {
            const int kb = ks * 16;
            uint32_t af[4];
            {
                const uint32_t addr =
                    sQ + (uint32_t)(((m0w + a_row) * AQ_STR + kb + a_col) * 2);
                ldsm_x4(af[0], af[1], af[2], af[3], addr);
            }
#pragma unroll
            for (int j = 0; j < 8; j++) {
                uint32_t b0, b1;
                const uint32_t addr =
                    sK + (uint32_t)(((8 * j + b_row) * AQ_STR + kb + b_col) * 2);
                ldsm_x2(b0, b1, addr);
                uint32_t bf2[2] = {b0, b1};
                mma16816(sacc[j], af, bf2);
            }
        }

        // Causal mask on diagonal-overlapping tiles
        if (k0 + AKT - 1 > q0) {
#pragma unroll
            for (int half = 0; half < 2; half++) {
                const int qrow = q0 + m0w + 8 * half + g;
#pragma unroll
                for (int j = 0; j < 8; j++)
#pragma unroll
                    for (int cc = 0; cc < 2; cc++) {
                        const int kcol = k0 + 8 * j + 2 * tig + cc;
                        if (kcol > qrow) sacc[j][2 * half + cc] = -1e30f;
                    }
            }
        }

        // Online softmax: rows are warp-private; reduce over 4 tig lanes
#pragma unroll
        for (int half = 0; half < 2; half++) {
            const int base = 2 * half;
            float mx = -1e30f;
#pragma unroll
            for (int j = 0; j < 8; j++)
                mx = fmaxf(mx, fmaxf(sacc[j][base], sacc[j][base + 1]));
            mx = fmaxf(mx, __shfl_xor_sync(0xffffffffu, mx, 1));
            mx = fmaxf(mx, __shfl_xor_sync(0xffffffffu, mx, 2));
            const float mnew = fmaxf(mrow[half], mx);
            float rs = 0.f;
#pragma unroll
            for (int j = 0; j < 8; j++) {
                const float p0 = __expf(sacc[j][base] - mnew);
                const float p1 = __expf(sacc[j][base + 1] - mnew);
                sacc[j][base] = p0;
                sacc[j][base + 1] = p1;
                rs += p0 + p1;
            }
            rs += __shfl_xor_sync(0xffffffffu, rs, 1);
            rs += __shfl_xor_sync(0xffffffffu, rs, 2);
            const float corr = __expf(mrow[half] - mnew);
            lrow[half] = lrow[half] * corr + rs;
            mrow[half] = mnew;
#pragma unroll
            for (int j = 0; j < 8; j++) {
                oacc[j][base] *= corr;
                oacc[j][base + 1] *= corr;
            }
        }

        __syncthreads();   // all S reads of Ke done before Pt overwrite

        // Write P split into Pt [ph|ph|pl]
        {
            const int r0 = m0w + g;
            const int r1 = m0w + 8 + g;
#pragma unroll
            for (int j = 0; j < 8; j++) {
                const int cc = 8 * j + 2 * tig;
#pragma unroll
                for (int c = 0; c < 2; c++) {
                    __nv_bfloat16 h, l;
                    bsplit(sacc[j][c], h, l);
                    Pt[r0 * AQ_STR + cc + c]       = h;
                    Pt[r0 * AQ_STR + 64 + cc + c]  = h;
                    Pt[r0 * AQ_STR + 128 + cc + c] = l;
                    bsplit(sacc[j][2 + c], h, l);
                    Pt[r1 * AQ_STR + cc + c]       = h;
                    Pt[r1 * AQ_STR + 64 + cc + c]  = h;
                    Pt[r1 * AQ_STR + 128 + cc + c] = l;
                }
            }
        }
        __syncthreads();

        // O += P' V' : warp tile 16(q) x 64(d) x 192
#pragma unroll
        for (int ks = 0; ks < 12; ks++) {
            const int kb = ks * 16;
            uint32_t af[4];
            {
                const uint32_t addr =
                    sP + (uint32_t)(((m0w + a_row) * AQ_STR + kb + a_col) * 2);
                ldsm_x4(af[0], af[1], af[2], af[3], addr);
            }
#pragma unroll
            for (int j = 0; j < 8; j++) {
                uint32_t b0, b1;
                const uint32_t addr =
                    sV + (uint32_t)(((8 * j + b_row) * AQ_STR + kb + b_col) * 2);
                ldsm_x2(b0, b1, addr);
                uint32_t bf2[2] = {b0, b1};
                mma16816(oacc[j], af, bf2);
            }
        }
    }

    // Normalize and write to (B,T,C)
    const int b = bh >> 4;
    const int h = bh & 15;
#pragma unroll
    for (int half = 0; half < 2; half++) {
        const float inv = 1.0f / lrow[half];
        const int t = q0 + m0w + 8 * half + g;
#pragma unroll
        for (int j = 0; j < 8; j++) {
            const int d = 8 * j + 2 * tig;
            float2 v = make_float2(oacc[j][2 * half] * inv,
                                   oacc[j][2 * half + 1] * inv);
            *(float2*)(g_Y + (size_t)(b * TSEQ + t) * CDIM + h * HDIM + d) = v;
        }
    }
}

// ---------------------------------------------------------------------------
extern "C" void kernel_launch(void* const* d_in, const int* in_sizes, int n_in,
                              void* d_out, int out_size)
{
    const float* x      = (const float*)d_in[0];
    const float* w_qkv  = (const float*)d_in[1];
    const float* b_qkv  = (const float*)d_in[2];
    const float* w_proj = (const float*)d_in[3];
    const float* b_proj = (const float*)d_in[4];
    float* out = (float*)d_out;

    // Resolve true DEVICE addresses of host-passed __device__ globals.
    void *p_xe = nullptr, *p_ye = nullptr, *p_wq = nullptr, *p_wp = nullptr,
         *p_Y = nullptr;
    cudaGetSymbolAddress(&p_xe, g_xe);
    cudaGetSymbolAddress(&p_ye, g_ye);
    cudaGetSymbolAddress(&p_wq, g_wqkv_t);
    cudaGetSymbolAddress(&p_wp, g_wproj_t);
    cudaGetSymbolAddress(&p_Y,  g_Y);
    __nv_bfloat16* xe = (__nv_bfloat16*)p_xe;
    __nv_bfloat16* ye = (__nv_bfloat16*)p_ye;
    __nv_bfloat16* wq = (__nv_bfloat16*)p_wq;
    __nv_bfloat16* wp = (__nv_bfloat16*)p_wp;
    float* Yd = (float*)p_Y;

    cudaFuncSetAttribute(attn_mma,
                         cudaFuncAttributeMaxDynamicSharedMemorySize,
                         A_SMEM_BYTES);

    convert_act<<<(MROWS * CDIM) / 256, 256>>>(x, xe);
    convert_wt<<<dim3(CDIM / 32, NQKV / 32), 256>>>(w_qkv, wq, NQKV);
    convert_wt<<<dim3(CDIM / 32, CDIM / 32), 256>>>(w_proj, wp, CDIM);

    mma_gemm<<<dim3(NQKV / 128, MROWS / 128), 256>>>(xe, wq, b_qkv, nullptr, 1);
    attn_mma<<<dim3(TSEQ / 128, BATCH * NHEADS), 256, A_SMEM_BYTES>>>();
    convert_act<<<(MROWS * CDIM) / 256, 256>>>(Yd, ye);
    mma_gemm<<<dim3(CDIM / 128, MROWS / 128), 256>>>(ye, wp, b_proj, out, 0);
}